// round 2
// baseline (speedup 1.0000x reference)
#include <cuda_runtime.h>
#include <cuda_bf16.h>

// Problem constants
#define NN 2048
#define DD 128
#define HH 64

typedef unsigned long long u64;

// ---------- scratch (device globals; no allocation allowed) ----------
__device__ float g_pi [NN * HH];   // agent @ W1a
__device__ float g_pjt[NN * HH];   // agent @ W1b + task @ W1c + b1
__device__ float g_pt [HH];        // task @ W1c + b1

// ---------- packed f32x2 helpers (sm_100+) ----------
__device__ __forceinline__ u64 f2add(u64 a, u64 b) {
    u64 r; asm("add.rn.f32x2 %0, %1, %2;" : "=l"(r) : "l"(a), "l"(b)); return r;
}
__device__ __forceinline__ u64 f2fma(u64 a, u64 b, u64 c) {
    u64 r; asm("fma.rn.f32x2 %0, %1, %2, %3;" : "=l"(r) : "l"(a), "l"(b), "l"(c)); return r;
}
__device__ __forceinline__ u64 pck(float x, float y) {
    u64 r; asm("mov.b64 %0, {%1, %2};" : "=l"(r) : "f"(x), "f"(y)); return r;
}
__device__ __forceinline__ float2 upk(u64 v) {
    float2 r; asm("mov.b64 {%0, %1}, %2;" : "=f"(r.x), "=f"(r.y) : "l"(v)); return r;
}

// ---------- k0: pt[h] = task . W1c[:,h] + b1[h] ----------
__global__ void k0_task(const float* __restrict__ z,
                        const float* __restrict__ W1,
                        const float* __restrict__ b1) {
    int h = threadIdx.x;                       // 64 threads
    const float* zt = z + NN * DD;             // task row z[2048]
    float t = b1[h];
#pragma unroll 8
    for (int k = 0; k < DD; k++)
        t = fmaf(zt[k], W1[(2 * DD + k) * HH + h], t);
    g_pt[h] = t;
}

// ---------- k1: pi / pjt projections (16 rows per block) ----------
__global__ __launch_bounds__(256) void k1_proj(const float* __restrict__ z,
                                               const float* __restrict__ W1) {
    __shared__ float zs[16][DD];
    int tid = threadIdx.x;
    int hp  = tid & 31;         // h pair index -> h = 2*hp
    int rr  = tid >> 5;         // 0..7, two rows each
    int row_base = blockIdx.x * 16;

    // stage 16 z rows (2048 floats) as float4
    for (int idx = tid; idx < 16 * DD / 4; idx += 256) {
        int r = idx >> 5;                // 32 float4 per row
        int c = (idx & 31) << 2;
        *(float4*)&zs[r][c] = *(const float4*)&z[(row_base + r) * DD + c];
    }
    __syncthreads();

    int r0 = rr * 2, r1 = r0 + 1;
    float2 a0 = {0.f, 0.f}, a1 = {0.f, 0.f};
    float2 b0 = {0.f, 0.f}, b1v = {0.f, 0.f};
#pragma unroll 8
    for (int k = 0; k < DD; k++) {
        float2 wa = *(const float2*)&W1[k * HH + 2 * hp];
        float2 wb = *(const float2*)&W1[(DD + k) * HH + 2 * hp];
        float z0 = zs[r0][k], z1 = zs[r1][k];
        a0.x  = fmaf(z0, wa.x, a0.x);  a0.y  = fmaf(z0, wa.y, a0.y);
        a1.x  = fmaf(z1, wa.x, a1.x);  a1.y  = fmaf(z1, wa.y, a1.y);
        b0.x  = fmaf(z0, wb.x, b0.x);  b0.y  = fmaf(z0, wb.y, b0.y);
        b1v.x = fmaf(z1, wb.x, b1v.x); b1v.y = fmaf(z1, wb.y, b1v.y);
    }
    float2 pt2 = *(const float2*)&g_pt[2 * hp];
    int gr0 = row_base + r0, gr1 = row_base + r1;
    *(float2*)&g_pi[gr0 * HH + 2 * hp] = a0;
    *(float2*)&g_pi[gr1 * HH + 2 * hp] = a1;
    b0.x += pt2.x;  b0.y += pt2.y;
    b1v.x += pt2.x; b1v.y += pt2.y;
    *(float2*)&g_pjt[gr0 * HH + 2 * hp] = b0;
    *(float2*)&g_pjt[gr1 * HH + 2 * hp] = b1v;
}

// ---------- main: out[i,j] = sigmoid(w_ij + gumbel(eps)) ----------
// CTA tile: 128 (i) x 64 (j). 256 threads = 16 tx * 16 ty.
// Thread tile: 8 i x 4 j, packed f32x2 accumulators over h-pairs.
#define TI 128
#define TJ 64
#define PJT_STRIDE 66            // pad: conflict-free LDS.64 across tx

__global__ __launch_bounds__(256) void main_kernel(const float* __restrict__ W2,
                                                   const float* __restrict__ b2,
                                                   const float* __restrict__ eps,
                                                   float* __restrict__ out) {
    extern __shared__ float smem[];
    float* pi_s  = smem;                       // 128 * 64
    float* pjt_s = smem + TI * HH;             // 64 rows * 66
    float* c_s   = pjt_s + TJ * PJT_STRIDE;    // 64 (W2)

    int tid = threadIdx.x;
    int tx = tid & 15, ty = tid >> 4;
    int it0 = blockIdx.y * TI;
    int jt0 = blockIdx.x * TJ;

    // stage pi tile (float4, stride 64 = aligned)
    for (int idx = tid; idx < TI * HH / 4; idx += 256) {
        int r = idx >> 4;                 // 16 float4 per row
        int c = (idx & 15) << 2;
        *(float4*)&pi_s[r * HH + c] = *(const float4*)&g_pi[(it0 + r) * HH + c];
    }
    // stage pjt tile (float2 into padded stride 66)
    for (int idx = tid; idx < TJ * HH / 2; idx += 256) {
        int r = idx >> 5;                 // 32 float2 per row
        int c = (idx & 31) << 1;
        *(float2*)&pjt_s[r * PJT_STRIDE + c] = *(const float2*)&g_pjt[(jt0 + r) * HH + c];
    }
    if (tid < HH) c_s[tid] = W2[tid];
    __syncthreads();

    u64 acc[8][4];
#pragma unroll
    for (int r = 0; r < 8; r++)
#pragma unroll
        for (int q = 0; q < 4; q++) acc[r][q] = 0ull;

#pragma unroll 4
    for (int hp = 0; hp < HH / 2; hp++) {
        u64 c2 = *(const u64*)&c_s[2 * hp];
        u64 a[8], b[4];
#pragma unroll
        for (int r = 0; r < 8; r++)
            a[r] = *(const u64*)&pi_s[(ty + 16 * r) * HH + 2 * hp];
#pragma unroll
        for (int q = 0; q < 4; q++)
            b[q] = *(const u64*)&pjt_s[(tx + 16 * q) * PJT_STRIDE + 2 * hp];
#pragma unroll
        for (int r = 0; r < 8; r++) {
#pragma unroll
            for (int q = 0; q < 4; q++) {
                u64 t = f2add(a[r], b[q]);           // fma pipe
                float2 tf = upk(t);
                tf.x = fmaxf(tf.x, 0.f);             // alu pipe (FMNMX)
                tf.y = fmaxf(tf.y, 0.f);             // alu pipe
                acc[r][q] = f2fma(pck(tf.x, tf.y), c2, acc[r][q]); // fma pipe
            }
        }
    }

    float b2v = b2[0];
#pragma unroll
    for (int r = 0; r < 8; r++) {
#pragma unroll
        for (int q = 0; q < 4; q++) {
            float2 s = upk(acc[r][q]);
            float w = s.x + s.y + b2v;
            int i = it0 + ty + 16 * r;
            int j = jt0 + tx + 16 * q;
            float e = eps[i * NN + j] + 1e-8f;
            // sigmoid(w + log e - log(1-e)) = e / (e + exp(-w)*(1-e))
            float qe = __expf(-w);
            float d  = fmaf(-qe, e, qe) + e;          // qe*(1-e) + e
            out[i * NN + j] = __fdividef(e, d);
        }
    }
}

// ---------- launch ----------
extern "C" void kernel_launch(void* const* d_in, const int* in_sizes, int n_in,
                              void* d_out, int out_size) {
    const float* z   = (const float*)d_in[0];   // (2049, 128)
    const float* W1  = (const float*)d_in[1];   // (384, 64)
    const float* b1  = (const float*)d_in[2];   // (64,)
    const float* W2  = (const float*)d_in[3];   // (64, 1)
    const float* b2  = (const float*)d_in[4];   // (1,)
    const float* eps = (const float*)d_in[5];   // (2048, 2048)
    float* out = (float*)d_out;                 // (2048, 2048)

    k0_task<<<1, 64>>>(z, W1, b1);
    k1_proj<<<NN / 16, 256>>>(z, W1);

    size_t smem_bytes = (TI * HH + TJ * PJT_STRIDE + HH) * sizeof(float); // 49920
    cudaFuncSetAttribute(main_kernel, cudaFuncAttributeMaxDynamicSharedMemorySize,
                         (int)smem_bytes);
    dim3 grid(NN / TJ, NN / TI);   // 32 x 16 = 512 CTAs
    main_kernel<<<grid, 256, smem_bytes>>>(W2, b2, eps, out);
}